// round 3
// baseline (speedup 1.0000x reference)
#include <cuda_runtime.h>
#include <math.h>

#define BB 4
#define CC 64
#define HH 128
#define WW 128
#define DD 256
#define NN 100
#define MAXDET 10
#define HWP (HH*WW)
#define SEG_OFF   0
#define MASK_OFF  (HWP*BB)
#define KEPT_OFF  (MASK_OFF + HWP*BB)
#define VALID_OFF (KEPT_OFF + BB*MAXDET*5)

#define TP 16                    // pixels per tile
#define CHUNKS 19                // ceil(17*17 / 16)

// ---------------- device scratch ----------------
__device__ int   g_ibox[BB][MAXDET][4];
__device__ int   g_valid[BB][MAXDET];
__device__ float g_seg0;

typedef unsigned long long ull;

// ---------------- packed f32x2 helpers (sm_103a) ----------------
__device__ __forceinline__ ull fma2(ull a, ull b, ull c) {
    ull d;
    asm("fma.rn.f32x2 %0, %1, %2, %3;" : "=l"(d) : "l"(a), "l"(b), "l"(c));
    return d;
}
__device__ __forceinline__ ull add2(ull a, ull b) {
    ull d;
    asm("add.rn.f32x2 %0, %1, %2;" : "=l"(d) : "l"(a), "l"(b));
    return d;
}
__device__ __forceinline__ ull pack2(float x) {
    unsigned u = __float_as_uint(x);
    ull r;
    asm("mov.b64 %0, {%1, %2};" : "=l"(r) : "r"(u), "r"(u));
    return r;
}
__device__ __forceinline__ void unpack2(ull v, float& lo, float& hi) {
    unsigned a, b;
    asm("mov.b64 {%0, %1}, %2;" : "=r"(a), "=r"(b) : "l"(v));
    lo = __uint_as_float(a);
    hi = __uint_as_float(b);
}

// ---------------- Kernel 1: NMS (blocks 0-3) + seg0 (block 4) ----------
__global__ void __launch_bounds__(256) front_kernel(
        const float* __restrict__ rb,
        const float* __restrict__ b1v, const float* __restrict__ W2,
        const float* __restrict__ b2v, const float* __restrict__ W3,
        const float* __restrict__ b3v,
        float* __restrict__ out) {
    const int t = threadIdx.x;   // 256

    if (blockIdx.x == BB) {
        // ---- seg0: MLP applied to the all-zero word ----
        __shared__ float h1c[DD];
        __shared__ float red[DD];
        h1c[t] = fmaxf(b1v[t], 0.f);
        __syncthreads();
        float acc = b2v[t];
        for (int d = 0; d < DD; d++) acc += h1c[d] * W2[d*DD + t];
        float h2 = fmaxf(acc, 0.f);
        red[t] = h2 * W3[t];
        __syncthreads();
        for (int off = 128; off; off >>= 1) {
            if (t < off) red[t] += red[t + off];
            __syncthreads();
        }
        if (t == 0) g_seg0 = red[0] + b3v[0];
        return;
    }

    const int b = blockIdx.x;
    __shared__ float bx[NN*5];
    __shared__ float area[NN];
    __shared__ float iou[NN*NN];
    __shared__ int   cand[NN];
    __shared__ float rv[256];
    __shared__ int   ri[256];
    __shared__ int   s_any;
    __shared__ int   idxs[MAXDET];
    __shared__ int   hasA[MAXDET];

    for (int i = t; i < NN*5; i += 256) bx[i] = rb[b*NN*5 + i];
    if (t == 0) s_any = 0;
    __syncthreads();

    if (t < NN) {
        float a = fmaxf(bx[t*5+2]-bx[t*5+0], 0.f) * fmaxf(bx[t*5+3]-bx[t*5+1], 0.f);
        area[t] = a;
        if (bx[t*5+4] > 0.2f) atomicOr(&s_any, 1);
    }
    __syncthreads();

    for (int k = t; k < NN*NN; k += 256) {
        int i = k / NN, j = k - i*NN;
        float lx = fmaxf(bx[i*5+0], bx[j*5+0]);
        float ly = fmaxf(bx[i*5+1], bx[j*5+1]);
        float rx = fminf(bx[i*5+2], bx[j*5+2]);
        float ry = fminf(bx[i*5+3], bx[j*5+3]);
        float iw = fmaxf(rx - lx, 0.f);
        float ih = fmaxf(ry - ly, 0.f);
        float inter = iw * ih;
        iou[k] = inter / (area[i] + area[j] - inter + 1e-9f);
    }
    if (t < NN) cand[t] = s_any ? (bx[t*5+4] > 0.2f ? 1 : 0) : 1;
    __syncthreads();

    for (int it = 0; it < MAXDET; it++) {
        float sc = (t < NN && cand[t]) ? bx[t*5+4] : -INFINITY;
        rv[t] = sc; ri[t] = t;
        __syncthreads();
        for (int off = 128; off; off >>= 1) {
            if (t < off) {
                float v2 = rv[t+off]; int i2 = ri[t+off];
                if (v2 > rv[t] || (v2 == rv[t] && i2 < ri[t])) { rv[t] = v2; ri[t] = i2; }
            }
            __syncthreads();
        }
        int  bi  = ri[0];
        bool has = rv[0] > -INFINITY;
        if (t == 0) { idxs[it] = bi; hasA[it] = has ? 1 : 0; }
        if (has && t < NN) {
            if (iou[bi*NN + t] > 0.4f || t == bi) cand[t] = 0;
        }
        __syncthreads();
    }

    if (t < MAXDET*5) {
        int det = t / 5, k = t - det*5;
        out[KEPT_OFF + b*MAXDET*5 + t] = bx[idxs[det]*5 + k];
    }
    if (t < MAXDET) {
        int kr = idxs[t];
        float x1f = bx[kr*5+0], y1f = bx[kr*5+1];
        float x2f = bx[kr*5+2], y2f = bx[kr*5+3];
        int v = hasA[t] && (x2f - x1f >= 1.f) && (y2f - y1f >= 1.f)
                        && (s_any ? 1 : (t < 5));
        out[VALID_OFF + b*MAXDET + t] = v ? 1.f : 0.f;
        g_valid[b][t] = v;
        int x1 = (int)floorf(x1f + 0.5f); x1 = min(max(x1, 0), WW);
        int y1 = (int)floorf(y1f + 0.5f); y1 = min(max(y1, 0), HH);
        int x2 = (int)floorf(x2f + 0.5f); x2 = min(max(x2, 0), WW);
        int y2 = (int)floorf(y2f + 0.5f); y2 = min(max(y2, 0), HH);
        g_ibox[b][t][0] = x1; g_ibox[b][t][1] = y1;
        g_ibox[b][t][2] = x2; g_ibox[b][t][3] = y2;
    }
}

// ---------------- Kernel 2: mask + default seg ----------------
__global__ void mask_kernel(float* __restrict__ out) {
    int gid = blockIdx.x * blockDim.x + threadIdx.x;
    if (gid >= BB*HWP) return;
    int b = gid >> 14;
    int p = gid & (HWP - 1);
    int h = p >> 7;
    int w = p & (WW - 1);
    bool inside = false;
    #pragma unroll
    for (int k = 0; k < MAXDET; k++) {
        if (g_valid[b][k]) {
            int x1 = g_ibox[b][k][0], y1 = g_ibox[b][k][1];
            int x2 = g_ibox[b][k][2], y2 = g_ibox[b][k][3];
            inside |= (w >= x1 && w < x2 && h >= y1 && h < y2);
        }
    }
    out[MASK_OFF + gid] = inside ? 0.f : 1.f;
    out[SEG_OFF + p*BB + b] = g_seg0;
}

// ---------------- layer: 2 features/thread, 2-way k-split, f32x2 -------
// in[d][px] -> outp[f][px]; partials of kp==1 staged in outp rows.
template<int KTOT, bool RELU>
__device__ __forceinline__ void layerF(
        const float* __restrict__ Wm, const float* __restrict__ bias,
        const float (*in)[TP], float (*outp)[TP],
        int t, int kp) {
    ull accA[8], accB[8];
    if (kp == 0) {
        ull bA = pack2(bias[t]);
        ull bB = pack2(bias[t + 128]);
        #pragma unroll
        for (int i = 0; i < 8; i++) { accA[i] = bA; accB[i] = bB; }
    } else {
        #pragma unroll
        for (int i = 0; i < 8; i++) { accA[i] = 0; accB[i] = 0; }
    }
    const int kh = KTOT >> 1;
    const int k0 = kp * kh;
    #pragma unroll 4
    for (int d = k0; d < k0 + kh; d++) {
        ull wA = pack2(Wm[d*DD + t]);
        ull wB = pack2(Wm[d*DD + t + 128]);
        const ulonglong2* row = (const ulonglong2*)&in[d][0];
        ulonglong2 r0 = row[0], r1 = row[1], r2 = row[2], r3 = row[3];
        accA[0] = fma2(wA, r0.x, accA[0]);
        accA[1] = fma2(wA, r0.y, accA[1]);
        accA[2] = fma2(wA, r1.x, accA[2]);
        accA[3] = fma2(wA, r1.y, accA[3]);
        accA[4] = fma2(wA, r2.x, accA[4]);
        accA[5] = fma2(wA, r2.y, accA[5]);
        accA[6] = fma2(wA, r3.x, accA[6]);
        accA[7] = fma2(wA, r3.y, accA[7]);
        accB[0] = fma2(wB, r0.x, accB[0]);
        accB[1] = fma2(wB, r0.y, accB[1]);
        accB[2] = fma2(wB, r1.x, accB[2]);
        accB[3] = fma2(wB, r1.y, accB[3]);
        accB[4] = fma2(wB, r2.x, accB[4]);
        accB[5] = fma2(wB, r2.y, accB[5]);
        accB[6] = fma2(wB, r3.x, accB[6]);
        accB[7] = fma2(wB, r3.y, accB[7]);
    }
    if (kp == 1) {
        ulonglong2* dA = (ulonglong2*)&outp[t][0];
        dA[0] = make_ulonglong2(accA[0], accA[1]);
        dA[1] = make_ulonglong2(accA[2], accA[3]);
        dA[2] = make_ulonglong2(accA[4], accA[5]);
        dA[3] = make_ulonglong2(accA[6], accA[7]);
        ulonglong2* dB = (ulonglong2*)&outp[t + 128][0];
        dB[0] = make_ulonglong2(accB[0], accB[1]);
        dB[1] = make_ulonglong2(accB[2], accB[3]);
        dB[2] = make_ulonglong2(accB[4], accB[5]);
        dB[3] = make_ulonglong2(accB[6], accB[7]);
    }
    __syncthreads();
    if (kp == 0) {
        const ulonglong2* sA2 = (const ulonglong2*)&outp[t][0];
        ulonglong2 qa0 = sA2[0], qa1 = sA2[1], qa2 = sA2[2], qa3 = sA2[3];
        const ulonglong2* sB2 = (const ulonglong2*)&outp[t + 128][0];
        ulonglong2 qb0 = sB2[0], qb1 = sB2[1], qb2 = sB2[2], qb3 = sB2[3];
        accA[0] = add2(accA[0], qa0.x); accA[1] = add2(accA[1], qa0.y);
        accA[2] = add2(accA[2], qa1.x); accA[3] = add2(accA[3], qa1.y);
        accA[4] = add2(accA[4], qa2.x); accA[5] = add2(accA[5], qa2.y);
        accA[6] = add2(accA[6], qa3.x); accA[7] = add2(accA[7], qa3.y);
        accB[0] = add2(accB[0], qb0.x); accB[1] = add2(accB[1], qb0.y);
        accB[2] = add2(accB[2], qb1.x); accB[3] = add2(accB[3], qb1.y);
        accB[4] = add2(accB[4], qb2.x); accB[5] = add2(accB[5], qb2.y);
        accB[6] = add2(accB[6], qb3.x); accB[7] = add2(accB[7], qb3.y);
        float va[16], vb[16];
        #pragma unroll
        for (int i = 0; i < 8; i++) {
            unpack2(accA[i], va[2*i], va[2*i+1]);
            unpack2(accB[i], vb[2*i], vb[2*i+1]);
        }
        if (RELU) {
            #pragma unroll
            for (int i = 0; i < 16; i++) { va[i] = fmaxf(va[i], 0.f); vb[i] = fmaxf(vb[i], 0.f); }
        }
        float4* oA = (float4*)&outp[t][0];
        float4* oB = (float4*)&outp[t + 128][0];
        #pragma unroll
        for (int i = 0; i < 4; i++) {
            oA[i] = make_float4(va[4*i], va[4*i+1], va[4*i+2], va[4*i+3]);
            oB[i] = make_float4(vb[4*i], vb[4*i+1], vb[4*i+2], vb[4*i+3]);
        }
    }
    __syncthreads();
}

// ---------------- Kernel 3: per-box-chunk MLP ----------------
__global__ void __launch_bounds__(256) mlp_kernel(
        const float* __restrict__ x,
        const float* __restrict__ W_sem, const float* __restrict__ b_sem,
        const float* __restrict__ W1, const float* __restrict__ b1,
        const float* __restrict__ W2, const float* __restrict__ b2,
        const float* __restrict__ W3, const float* __restrict__ b3,
        float* __restrict__ out) {
    __shared__ __align__(16) float sx[CC][TP];
    __shared__ __align__(16) float sA[DD][TP];
    __shared__ __align__(16) float sB[DD][TP];
    __shared__ int spix[TP];

    const int b   = blockIdx.z;
    const int det = blockIdx.y;
    if (!g_valid[b][det]) return;
    const int x1 = g_ibox[b][det][0], y1 = g_ibox[b][det][1];
    const int x2 = g_ibox[b][det][2], y2 = g_ibox[b][det][3];
    const int wdt = x2 - x1;
    const int area = wdt * (y2 - y1);
    const int base = blockIdx.x * TP;
    if (base >= area) return;
    const int rem = min(area - base, TP);

    const int tid = threadIdx.x;
    if (tid < TP) {
        int idx = base + (tid < rem ? tid : 0);
        int py = y1 + idx / wdt;
        int px = x1 + idx % wdt;
        spix[tid] = py * WW + px;
    }
    __syncthreads();

    for (int i = tid; i < CC*TP; i += 256) {
        int c = i >> 4, p = i & (TP - 1);
        sx[c][p] = x[((b << 6) + c) * HWP + spix[p]];
    }
    __syncthreads();

    const int t  = tid & 127;
    const int kp = tid >> 7;
    layerF<CC,  false>(W_sem, b_sem, sx, sA, t, kp);
    layerF<DD,  true >(W1,    b1,    sA, sB, t, kp);
    layerF<DD,  true >(W2,    b2,    sB, sA, t, kp);

    // final dot: half-warp per pixel
    const int w  = tid >> 5;
    const int l  = tid & 31;
    const int p  = w * 2 + (l >> 4);
    const int sl = l & 15;
    if (p < rem) {
        float s = 0.f;
        #pragma unroll
        for (int j = sl; j < DD; j += 16) s += sA[j][p] * W3[j];
        #pragma unroll
        for (int off = 8; off; off >>= 1)
            s += __shfl_down_sync(0xffffffffu, s, off, 16);
        if (sl == 0) out[SEG_OFF + spix[p]*BB + b] = s + b3[0];
    }
}

// ---------------- launch ----------------
extern "C" void kernel_launch(void* const* d_in, const int* in_sizes, int n_in,
                              void* d_out, int out_size) {
    (void)in_sizes; (void)n_in; (void)out_size;
    const float* x     = (const float*)d_in[0];
    const float* rb    = (const float*)d_in[1];
    const float* W_sem = (const float*)d_in[2];
    const float* b_sem = (const float*)d_in[3];
    const float* W1    = (const float*)d_in[4];
    const float* b1    = (const float*)d_in[5];
    const float* W2    = (const float*)d_in[6];
    const float* b2    = (const float*)d_in[7];
    const float* W3    = (const float*)d_in[8];
    const float* b3    = (const float*)d_in[9];
    float* out = (float*)d_out;

    front_kernel<<<BB + 1, 256>>>(rb, b1, W2, b2, W3, b3, out);
    mask_kernel<<<(BB*HWP)/256, 256>>>(out);
    mlp_kernel<<<dim3(CHUNKS, MAXDET, BB), 256>>>(x, W_sem, b_sem, W1, b1, W2, b2, W3, b3, out);
}